// round 1
// baseline (speedup 1.0000x reference)
#include <cuda_runtime.h>

// BackgroundStd2D: masked per-(b,c) std over HW.
// bf: (4,256,256,256) f32, mask: (4,1,256,256) f32, min_std: (1,256,1,1) f32
// out: (4,256,1,1) f32 = max(std_bc, 1e-6 + min_std[c])

#define B 4
#define C 256
#define HW 65536   // 256*256

__global__ __launch_bounds__(256, 8)
void bgstd_kernel(const float* __restrict__ bf,
                  const float* __restrict__ mask,
                  const float* __restrict__ min_std,
                  float* __restrict__ out)
{
    const int bc = blockIdx.x;        // 0..1023
    const int b  = bc >> 8;           // /C
    const int c  = bc & (C - 1);

    const float4* __restrict__ bf4 = reinterpret_cast<const float4*>(bf + (size_t)bc * HW);
    const float4* __restrict__ m4  = reinterpret_cast<const float4*>(mask + (size_t)b * HW);

    float n = 0.0f, s = 0.0f, sq = 0.0f;

    const int tid = threadIdx.x;
    // HW/4 = 16384 float4's, 256 threads -> 64 iters/thread
    #pragma unroll 4
    for (int i = tid; i < HW / 4; i += 256) {
        float4 v = bf4[i];
        float4 m = m4[i];
        float k0 = (m.x <= 0.5f) ? 1.0f : 0.0f;
        float k1 = (m.y <= 0.5f) ? 1.0f : 0.0f;
        float k2 = (m.z <= 0.5f) ? 1.0f : 0.0f;
        float k3 = (m.w <= 0.5f) ? 1.0f : 0.0f;
        n += (k0 + k1) + (k2 + k3);
        s  = fmaf(v.x, k0, s);
        s  = fmaf(v.y, k1, s);
        s  = fmaf(v.z, k2, s);
        s  = fmaf(v.w, k3, s);
        sq = fmaf(v.x * v.x, k0, sq);
        sq = fmaf(v.y * v.y, k1, sq);
        sq = fmaf(v.z * v.z, k2, sq);
        sq = fmaf(v.w * v.w, k3, sq);
    }

    // warp reduce
    #pragma unroll
    for (int off = 16; off > 0; off >>= 1) {
        n  += __shfl_down_sync(0xFFFFFFFFu, n,  off);
        s  += __shfl_down_sync(0xFFFFFFFFu, s,  off);
        sq += __shfl_down_sync(0xFFFFFFFFu, sq, off);
    }

    __shared__ float sm_n[8], sm_s[8], sm_sq[8];
    const int wid = tid >> 5;
    const int lid = tid & 31;
    if (lid == 0) { sm_n[wid] = n; sm_s[wid] = s; sm_sq[wid] = sq; }
    __syncthreads();

    if (wid == 0) {
        n  = (lid < 8) ? sm_n[lid]  : 0.0f;
        s  = (lid < 8) ? sm_s[lid]  : 0.0f;
        sq = (lid < 8) ? sm_sq[lid] : 0.0f;
        #pragma unroll
        for (int off = 4; off > 0; off >>= 1) {
            n  += __shfl_down_sync(0xFFFFFFFFu, n,  off);
            s  += __shfl_down_sync(0xFFFFFFFFu, s,  off);
            sq += __shfl_down_sync(0xFFFFFFFFu, sq, off);
        }
        if (lid == 0) {
            // var = (sumsq - s^2/n) / (n-1)
            float var = (sq - s * s / n) / (n - 1.0f);
            float sd = sqrtf(var);
            float thresh = 1e-6f + min_std[c];   // MIN_STD_VAL/10 + min_std
            out[bc] = fmaxf(sd, thresh);
        }
    }
}

extern "C" void kernel_launch(void* const* d_in, const int* in_sizes, int n_in,
                              void* d_out, int out_size)
{
    const float* bf      = (const float*)d_in[0];
    const float* mask    = (const float*)d_in[1];
    const float* min_std = (const float*)d_in[2];
    float* out = (float*)d_out;

    bgstd_kernel<<<B * C, 256>>>(bf, mask, min_std, out);
}